// round 4
// baseline (speedup 1.0000x reference)
#include <cuda_runtime.h>
#include <cuda_bf16.h>
#include <stdint.h>

// Problem constants
#define N_ROWS 4096
#define C_CLS  1000
#define D_DIM  1024
#define NC_PER_T 4096000u          // N*C
#define SIG_OFF  4096000           // sigma offset in d_out (after mu_out)

// mu scratch (sigma lives in d_out directly)
__device__ float g_mu[N_ROWS * C_CLS];

// ---------------------------------------------------------------------------
// Threefry2x32-20, key (0, 42), PARTITIONABLE mode: ctr=(0,i), xor-fold out.
// ---------------------------------------------------------------------------
__device__ __forceinline__ uint32_t tf_fold(uint32_t ctr) {
    const uint32_t ks0 = 0u;
    const uint32_t ks1 = 42u;
    const uint32_t ks2 = 0x1BD11BDAu ^ 0u ^ 42u;
    uint32_t x0 = 0u + ks0;
    uint32_t x1 = ctr + ks1;
#define TFR(r) { x0 += x1; x1 = __funnelshift_l(x1, x1, (r)); x1 ^= x0; }
    TFR(13) TFR(15) TFR(26) TFR(6)
    x0 += ks1; x1 += ks2 + 1u;
    TFR(17) TFR(29) TFR(16) TFR(24)
    x0 += ks2; x1 += ks0 + 2u;
    TFR(13) TFR(15) TFR(26) TFR(6)
    x0 += ks0; x1 += ks1 + 3u;
    TFR(17) TFR(29) TFR(16) TFR(24)
    x0 += ks1; x1 += ks2 + 4u;
    TFR(13) TFR(15) TFR(26) TFR(6)
    x0 += ks2; x1 += ks0 + 5u;
#undef TFR
    return x0 ^ x1;
}

// bits -> uniform(-0.99999994, 1) -> sqrt(2)*erfinv(u)
__device__ __forceinline__ float bits_to_normal(uint32_t b) {
    float f = __uint_as_float((b >> 9) | 0x3f800000u) - 1.0f;   // [0,1)
    float u = fmaf(f, 2.0f, -0.99999994f);
    u = fmaxf(u, -0.99999994f);
    return 1.41421356f * erfinvf(u);
}

// ---------------------------------------------------------------------------
// GEMM v2: h = x @ W^T with fused epilogue, using fma.rn.f32x2 (dual fp32).
// Tile 128x128, 256 threads, 8x8 microtile, k packed in pairs (acc split
// into even/odd-k partial sums, folded in epilogue). 3-stage cp.async.
// smem layout: row-major [row][k] with stride 12 floats (48B, 16B-aligned).
// ---------------------------------------------------------------------------
#define KD 8
#define RSTRIDE 12
#define STAGE_F (256 * RSTRIDE)     // 128 A rows + 128 B rows per stage
#define NTILES  (D_DIM / KD)        // 128

typedef unsigned long long u64;

__device__ __forceinline__ void ffma2(u64& acc, u64 a, u64 b) {
    asm("fma.rn.f32x2 %0, %1, %2, %0;" : "+l"(acc) : "l"(a), "l"(b));
}

__global__ __launch_bounds__(256, 1) void gemm_kernel(
    const float* __restrict__ X, const float* __restrict__ W,
    float* __restrict__ out)
{
    __shared__ float sm[3 * STAGE_F];   // 36 KB

    const int tid = threadIdx.x;
    const int bm = blockIdx.y * 128;
    const int bn = blockIdx.x * 128;
    const int tm = (tid >> 4) << 3;
    const int tn = (tid & 15) << 3;

    // loader mapping: row = tid>>1 (0..127), half = (tid&1)*4 floats
    const int lr = tid >> 1;
    const int lh = (tid & 1) * 4;
    const float* gA = X + (size_t)(bm + lr) * D_DIM + lh;
    const int bj = bn + lr;
    const float* gB = W + (size_t)(bj < 2000 ? bj : 1999) * D_DIM + lh;
    const int bbytes = (bj < 2000) ? 16 : 0;

    const uint32_t smem_base = (uint32_t)__cvta_generic_to_shared(sm);
    const uint32_t dA = smem_base + (uint32_t)((lr * RSTRIDE + lh) * 4);
    const uint32_t dB = smem_base + (uint32_t)(((128 + lr) * RSTRIDE + lh) * 4);

#define ISSUE(t, b) { \
    uint32_t off = (uint32_t)((b) * STAGE_F * 4); \
    const float* sa = gA + (t) * KD; \
    const float* sb = gB + (t) * KD; \
    asm volatile("cp.async.cg.shared.global [%0], [%1], 16;" :: "r"(dA + off), "l"(sa)); \
    asm volatile("cp.async.cg.shared.global [%0], [%1], 16, %2;" :: "r"(dB + off), "l"(sb), "r"(bbytes)); \
    asm volatile("cp.async.commit_group;"); \
}

    u64 acc[64];
#pragma unroll
    for (int i = 0; i < 64; ++i) acc[i] = 0ull;

    ISSUE(0, 0)
    ISSUE(1, 1)

#pragma unroll 1
    for (int t = 0; t < NTILES; ++t) {
        if (t + 1 < NTILES) {
            asm volatile("cp.async.wait_group 1;");
        } else {
            asm volatile("cp.async.wait_group 0;");
        }
        __syncthreads();
        if (t + 2 < NTILES) {
            const int nb = (t + 2) % 3;
            ISSUE(t + 2, nb)
        }

        const float* As = sm + (t % 3) * STAGE_F;
        const float* Bs = As + 128 * RSTRIDE;

#pragma unroll
        for (int k2 = 0; k2 < KD / 2; ++k2) {
            u64 a2[8], b2[8];
#pragma unroll
            for (int i = 0; i < 8; ++i)
                a2[i] = *(const u64*)(As + (tm + i) * RSTRIDE + 2 * k2);
#pragma unroll
            for (int j = 0; j < 8; ++j)
                b2[j] = *(const u64*)(Bs + (tn + j) * RSTRIDE + 2 * k2);
#pragma unroll
            for (int i = 0; i < 8; ++i)
#pragma unroll
                for (int j = 0; j < 8; ++j)
                    ffma2(acc[i * 8 + j], a2[i], b2[j]);
        }
        __syncthreads();
    }
#undef ISSUE

    // Epilogue: fold lo+hi, route mu / sigma
#pragma unroll
    for (int i = 0; i < 8; ++i) {
        const int n = bm + tm + i;
#pragma unroll
        for (int j8 = 0; j8 < 8; ++j8) {
            const int j = bn + tn + j8;
            uint32_t lo, hi;
            asm("mov.b64 {%0, %1}, %2;" : "=r"(lo), "=r"(hi) : "l"(acc[i * 8 + j8]));
            const float v = __uint_as_float(lo) + __uint_as_float(hi);
            if (j < 1000) {
                g_mu[(size_t)n * C_CLS + j] = v;
            } else if (j < 2000) {
                out[SIG_OFF + (size_t)n * C_CLS + (j - 1000)] = __expf(0.5f * v);
            }
        }
    }
}

// ---------------------------------------------------------------------------
// Kernel B: per-n sampling + softmax + mean + exp (unchanged from R3 pass).
// ---------------------------------------------------------------------------
__global__ __launch_bounds__(256) void sample_kernel(float* __restrict__ out)
{
    __shared__ float wsum[2][2][8];   // [buf][pair 0/1][warp]

    const int n = blockIdx.x;
    const int tid = threadIdx.x;
    const int warp = tid >> 5;
    const int lane = tid & 31;
    const int c0 = tid << 2;
    const bool active = (c0 < C_CLS);
    const float* g_sigma = out + SIG_OFF;

    float mu[4] = {0.f, 0.f, 0.f, 0.f};
    float sg[4] = {0.f, 0.f, 0.f, 0.f};
    if (active) {
        float4 m4 = *(const float4*)(g_mu + (size_t)n * C_CLS + c0);
        float4 s4 = *(const float4*)(g_sigma + (size_t)n * C_CLS + c0);
        mu[0] = m4.x; mu[1] = m4.y; mu[2] = m4.z; mu[3] = m4.w;
        sg[0] = s4.x; sg[1] = s4.y; sg[2] = s4.z; sg[3] = s4.w;
    }

    float a0 = 0.f, a1 = 0.f, a2 = 0.f, a3 = 0.f;

#pragma unroll 1
    for (int tp = 0; tp < 16; ++tp) {
        const int buf = tp & 1;
        float q0[4], q1[4];
        float s0 = 0.f, s1 = 0.f;
        if (active) {
            const uint32_t ib = (uint32_t)tp * NC_PER_T + (uint32_t)n * 1000u + (uint32_t)c0;
#pragma unroll
            for (int j = 0; j < 4; ++j) {
                uint32_t b0 = tf_fold(ib + j);                      // t = tp
                uint32_t b1 = tf_fold(ib + j + 16u * NC_PER_T);     // t = tp+16
                float e0 = bits_to_normal(b0);
                float e1 = bits_to_normal(b1);
                q0[j] = __expf(fmaf(sg[j], e0, mu[j]));
                q1[j] = __expf(fmaf(sg[j], e1, mu[j]));
                s0 += q0[j]; s1 += q1[j];
            }
        } else {
#pragma unroll
            for (int j = 0; j < 4; ++j) { q0[j] = 0.f; q1[j] = 0.f; }
        }
#pragma unroll
        for (int off = 16; off; off >>= 1) {
            s0 += __shfl_xor_sync(0xffffffffu, s0, off);
            s1 += __shfl_xor_sync(0xffffffffu, s1, off);
        }
        if (lane == 0) {
            wsum[buf][0][warp] = s0;
            wsum[buf][1][warp] = s1;
        }
        __syncthreads();

        float t0 = 0.f, t1 = 0.f;
#pragma unroll
        for (int w = 0; w < 8; ++w) {
            t0 += wsum[buf][0][w];
            t1 += wsum[buf][1][w];
        }
        const float inv0 = __frcp_rn(t0);
        const float inv1 = __frcp_rn(t1);

        a0 = fmaf(q0[0], inv0, a0); a0 = fmaf(q1[0], inv1, a0);
        a1 = fmaf(q0[1], inv0, a1); a1 = fmaf(q1[1], inv1, a1);
        a2 = fmaf(q0[2], inv0, a2); a2 = fmaf(q1[2], inv1, a2);
        a3 = fmaf(q0[3], inv0, a3); a3 = fmaf(q1[3], inv1, a3);
    }

    if (active) {
        float4 o;
        o.x = __expf(a0 * 0.03125f);
        o.y = __expf(a1 * 0.03125f);
        o.z = __expf(a2 * 0.03125f);
        o.w = __expf(a3 * 0.03125f);
        *(float4*)(out + (size_t)n * C_CLS + c0) = o;
    }
}

// ---------------------------------------------------------------------------
extern "C" void kernel_launch(void* const* d_in, const int* in_sizes, int n_in,
                              void* d_out, int out_size)
{
    const float* X = (const float*)d_in[0];   // (4096, 1024)
    const float* W = (const float*)d_in[1];   // (2000, 1024)
    float* out = (float*)d_out;               // mu_out (4096,1000) ++ sigma (4096,1000)

    gemm_kernel<<<dim3(16, 32), 256>>>(X, W, out);
    sample_kernel<<<N_ROWS, 256>>>(out);
}

// round 5
// speedup vs baseline: 1.6219x; 1.6219x over previous
#include <cuda_runtime.h>
#include <cuda_bf16.h>
#include <stdint.h>

// Problem constants
#define N_ROWS 4096
#define C_CLS  1000
#define D_DIM  1024
#define NC_PER_T 4096000u          // N*C
#define SIG_OFF  4096000           // sigma offset in d_out (after mu_out)

// mu scratch (sigma lives in d_out directly)
__device__ float g_mu[N_ROWS * C_CLS];

// ---------------------------------------------------------------------------
// Threefry2x32-20, key (0, 42), PARTITIONABLE mode: ctr=(0,i), xor-fold out.
// ---------------------------------------------------------------------------
__device__ __forceinline__ uint32_t tf_fold(uint32_t ctr) {
    const uint32_t ks0 = 0u;
    const uint32_t ks1 = 42u;
    const uint32_t ks2 = 0x1BD11BDAu ^ 0u ^ 42u;
    uint32_t x0 = 0u + ks0;
    uint32_t x1 = ctr + ks1;
#define TFR(r) { x0 += x1; x1 = __funnelshift_l(x1, x1, (r)); x1 ^= x0; }
    TFR(13) TFR(15) TFR(26) TFR(6)
    x0 += ks1; x1 += ks2 + 1u;
    TFR(17) TFR(29) TFR(16) TFR(24)
    x0 += ks2; x1 += ks0 + 2u;
    TFR(13) TFR(15) TFR(26) TFR(6)
    x0 += ks0; x1 += ks1 + 3u;
    TFR(17) TFR(29) TFR(16) TFR(24)
    x0 += ks1; x1 += ks2 + 4u;
    TFR(13) TFR(15) TFR(26) TFR(6)
    x0 += ks2; x1 += ks0 + 5u;
#undef TFR
    return x0 ^ x1;
}

// bits -> uniform(-0.99999994, 1) -> sqrt(2)*erfinv(u)
__device__ __forceinline__ float bits_to_normal(uint32_t b) {
    float f = __uint_as_float((b >> 9) | 0x3f800000u) - 1.0f;   // [0,1)
    float u = fmaf(f, 2.0f, -0.99999994f);
    u = fmaxf(u, -0.99999994f);
    return 1.41421356f * erfinvf(u);
}

// ---------------------------------------------------------------------------
// GEMM v3: fma.rn.f32x2, conflict-free k2-major smem layout.
//   A stage: u64 Asm[4][128]  (k2-major, m contiguous)  -> reads broadcast
//   B stage: u64 Bsm[4][128]  at perm(n)=16*(n&7)+((n>>3)^(n&7))
//            -> reads lane-contiguous (conflict-free)
// 8-byte cp.async (a u64 = one k-pair), 3-stage ring, 24 KB smem.
// ---------------------------------------------------------------------------
#define KD 8
#define STAGE_U64 1024              // 512 A + 512 B u64 per stage
#define NTILES  (D_DIM / KD)        // 128

typedef unsigned long long u64;

__device__ __forceinline__ void ffma2(u64& acc, u64 a, u64 b) {
    asm("fma.rn.f32x2 %0, %1, %2, %0;" : "+l"(acc) : "l"(a), "l"(b));
}

__global__ __launch_bounds__(256, 1) void gemm_kernel(
    const float* __restrict__ X, const float* __restrict__ W,
    float* __restrict__ out)
{
    __shared__ u64 sm[3 * STAGE_U64];   // 24 KB

    const int tid = threadIdx.x;
    const int bm = blockIdx.y * 128;
    const int bn = blockIdx.x * 128;
    const int tm = (tid >> 4) << 3;
    const int lane16 = tid & 15;        // B column group for compute

    // loader mapping: row = tid>>1 (0..127), k-half = (tid&1)*4 floats
    const int lr = tid >> 1;
    const int lh = (tid & 1) * 4;
    const int k2w = lh >> 1;            // 0 or 2
    const float* gA = X + (size_t)(bm + lr) * D_DIM + lh;
    const int bj = bn + lr;
    const float* gB = W + (size_t)(bj < 2000 ? bj : 1999) * D_DIM + lh;
    const int bbytes = (bj < 2000) ? 8 : 0;
    const int permw = 16 * (lr & 7) + ((lr >> 3) ^ (lr & 7));

    const uint32_t smem_base = (uint32_t)__cvta_generic_to_shared(sm);
    const uint32_t dA0 = smem_base + (uint32_t)(((k2w + 0) * 128 + lr) * 8);
    const uint32_t dA1 = smem_base + (uint32_t)(((k2w + 1) * 128 + lr) * 8);
    const uint32_t dB0 = smem_base + (uint32_t)((512 + (k2w + 0) * 128 + permw) * 8);
    const uint32_t dB1 = smem_base + (uint32_t)((512 + (k2w + 1) * 128 + permw) * 8);

#define ISSUE(t, b) { \
    uint32_t off = (uint32_t)((b) * STAGE_U64 * 8); \
    const float* sa = gA + (t) * KD; \
    const float* sb = gB + (t) * KD; \
    asm volatile("cp.async.ca.shared.global [%0], [%1], 8;"     :: "r"(dA0 + off), "l"(sa)); \
    asm volatile("cp.async.ca.shared.global [%0], [%1], 8;"     :: "r"(dA1 + off), "l"(sa + 2)); \
    asm volatile("cp.async.ca.shared.global [%0], [%1], 8, %2;" :: "r"(dB0 + off), "l"(sb), "r"(bbytes)); \
    asm volatile("cp.async.ca.shared.global [%0], [%1], 8, %2;" :: "r"(dB1 + off), "l"(sb + 2), "r"(bbytes)); \
    asm volatile("cp.async.commit_group;"); \
}

    u64 acc[64];
#pragma unroll
    for (int i = 0; i < 64; ++i) acc[i] = 0ull;

    ISSUE(0, 0)
    ISSUE(1, 1)

#pragma unroll 1
    for (int t = 0; t < NTILES; ++t) {
        if (t + 1 < NTILES) {
            asm volatile("cp.async.wait_group 1;");
        } else {
            asm volatile("cp.async.wait_group 0;");
        }
        __syncthreads();
        if (t + 2 < NTILES) {
            const int nb = (t + 2) % 3;
            ISSUE(t + 2, nb)
        }

        const u64* As = sm + (t % 3) * STAGE_U64;
        const u64* Bs = As + 512;

#pragma unroll
        for (int k2 = 0; k2 < 4; ++k2) {
            u64 a2[8], b2[8];
#pragma unroll
            for (int i = 0; i < 8; ++i)
                a2[i] = As[k2 * 128 + tm + i];           // broadcast
#pragma unroll
            for (int j = 0; j < 8; ++j)
                b2[j] = Bs[k2 * 128 + 16 * j + (lane16 ^ j)];  // conflict-free
#pragma unroll
            for (int i = 0; i < 8; ++i)
#pragma unroll
                for (int j = 0; j < 8; ++j)
                    ffma2(acc[i * 8 + j], a2[i], b2[j]);
        }
        __syncthreads();
    }
#undef ISSUE

    // Epilogue: fold lo+hi, route mu / sigma.  logical n-col = tn + j
    const int tn = lane16 << 3;
#pragma unroll
    for (int i = 0; i < 8; ++i) {
        const int n = bm + tm + i;
#pragma unroll
        for (int j8 = 0; j8 < 8; ++j8) {
            const int j = bn + tn + j8;
            uint32_t lo, hi;
            asm("mov.b64 {%0, %1}, %2;" : "=r"(lo), "=r"(hi) : "l"(acc[i * 8 + j8]));
            const float v = __uint_as_float(lo) + __uint_as_float(hi);
            if (j < 1000) {
                g_mu[(size_t)n * C_CLS + j] = v;
            } else if (j < 2000) {
                out[SIG_OFF + (size_t)n * C_CLS + (j - 1000)] = __expf(0.5f * v);
            }
        }
    }
}

// ---------------------------------------------------------------------------
// Kernel B: per-n sampling + softmax + mean + exp (unchanged; passing).
// ---------------------------------------------------------------------------
__global__ __launch_bounds__(256) void sample_kernel(float* __restrict__ out)
{
    __shared__ float wsum[2][2][8];   // [buf][pair 0/1][warp]

    const int n = blockIdx.x;
    const int tid = threadIdx.x;
    const int warp = tid >> 5;
    const int lane = tid & 31;
    const int c0 = tid << 2;
    const bool active = (c0 < C_CLS);
    const float* g_sigma = out + SIG_OFF;

    float mu[4] = {0.f, 0.f, 0.f, 0.f};
    float sg[4] = {0.f, 0.f, 0.f, 0.f};
    if (active) {
        float4 m4 = *(const float4*)(g_mu + (size_t)n * C_CLS + c0);
        float4 s4 = *(const float4*)(g_sigma + (size_t)n * C_CLS + c0);
        mu[0] = m4.x; mu[1] = m4.y; mu[2] = m4.z; mu[3] = m4.w;
        sg[0] = s4.x; sg[1] = s4.y; sg[2] = s4.z; sg[3] = s4.w;
    }

    float a0 = 0.f, a1 = 0.f, a2 = 0.f, a3 = 0.f;

#pragma unroll 1
    for (int tp = 0; tp < 16; ++tp) {
        const int buf = tp & 1;
        float q0[4], q1[4];
        float s0 = 0.f, s1 = 0.f;
        if (active) {
            const uint32_t ib = (uint32_t)tp * NC_PER_T + (uint32_t)n * 1000u + (uint32_t)c0;
#pragma unroll
            for (int j = 0; j < 4; ++j) {
                uint32_t b0 = tf_fold(ib + j);                      // t = tp
                uint32_t b1 = tf_fold(ib + j + 16u * NC_PER_T);     // t = tp+16
                float e0 = bits_to_normal(b0);
                float e1 = bits_to_normal(b1);
                q0[j] = __expf(fmaf(sg[j], e0, mu[j]));
                q1[j] = __expf(fmaf(sg[j], e1, mu[j]));
                s0 += q0[j]; s1 += q1[j];
            }
        } else {
#pragma unroll
            for (int j = 0; j < 4; ++j) { q0[j] = 0.f; q1[j] = 0.f; }
        }
#pragma unroll
        for (int off = 16; off; off >>= 1) {
            s0 += __shfl_xor_sync(0xffffffffu, s0, off);
            s1 += __shfl_xor_sync(0xffffffffu, s1, off);
        }
        if (lane == 0) {
            wsum[buf][0][warp] = s0;
            wsum[buf][1][warp] = s1;
        }
        __syncthreads();

        float t0 = 0.f, t1 = 0.f;
#pragma unroll
        for (int w = 0; w < 8; ++w) {
            t0 += wsum[buf][0][w];
            t1 += wsum[buf][1][w];
        }
        const float inv0 = __frcp_rn(t0);
        const float inv1 = __frcp_rn(t1);

        a0 = fmaf(q0[0], inv0, a0); a0 = fmaf(q1[0], inv1, a0);
        a1 = fmaf(q0[1], inv0, a1); a1 = fmaf(q1[1], inv1, a1);
        a2 = fmaf(q0[2], inv0, a2); a2 = fmaf(q1[2], inv1, a2);
        a3 = fmaf(q0[3], inv0, a3); a3 = fmaf(q1[3], inv1, a3);
    }

    if (active) {
        float4 o;
        o.x = __expf(a0 * 0.03125f);
        o.y = __expf(a1 * 0.03125f);
        o.z = __expf(a2 * 0.03125f);
        o.w = __expf(a3 * 0.03125f);
        *(float4*)(out + (size_t)n * C_CLS + c0) = o;
    }
}

// ---------------------------------------------------------------------------
extern "C" void kernel_launch(void* const* d_in, const int* in_sizes, int n_in,
                              void* d_out, int out_size)
{
    const float* X = (const float*)d_in[0];   // (4096, 1024)
    const float* W = (const float*)d_in[1];   // (2000, 1024)
    float* out = (float*)d_out;               // mu_out (4096,1000) ++ sigma (4096,1000)

    gemm_kernel<<<dim3(16, 32), 256>>>(X, W, out);
    sample_kernel<<<N_ROWS, 256>>>(out);
}